// round 9
// baseline (speedup 1.0000x reference)
#include <cuda_runtime.h>
#include <math.h>

#define T_TOK 524288
#define D_DIM 256
#define N_SEG 8192

__device__ __align__(16) float g_mean[N_SEG * D_DIM];
__device__ __align__(16) float g_tg[N_SEG * D_DIM];
__device__ int g_segstart[N_SEG + 1];

#define FFMA2(acc, a, b) \
    asm("fma.rn.f32x2 %0, %1, %2, %0;" : "+l"(acc) : "l"(a), "l"(b))

// ---------------------------------------------------------------------------
// Pass 0: segment boundaries from sorted obj.
// ---------------------------------------------------------------------------
__global__ void k_bounds(const int* __restrict__ obj) {
    int t = blockIdx.x * blockDim.x + threadIdx.x;
    if (t >= T_TOK) return;
    if (t == 0) {
        int v0 = obj[0];
        for (int j = 0; j <= v0; ++j) g_segstart[j] = 0;
        int vl = obj[T_TOK - 1];
        for (int j = vl + 1; j <= N_SEG; ++j) g_segstart[j] = T_TOK;
    } else {
        int p = obj[t - 1], c = obj[t];
        for (int j = p + 1; j <= c; ++j) g_segstart[j] = t;
    }
}

// ---------------------------------------------------------------------------
// Pass 1: per-segment mean. One 512-thread block per segment; thread owns
// float4 column (tid&63)*4 of row-group tid>>6 (8 groups, stride 8).
// ---------------------------------------------------------------------------
__global__ void __launch_bounds__(512)
k_segmean(const float* __restrict__ emb) {
    int n = blockIdx.x, tid = threadIdx.x;
    __shared__ __align__(16) float red[8][256];
    int s = g_segstart[n], e = g_segstart[n + 1];

    int r = tid >> 6;
    int c4 = (tid & 63) * 4;
    const float4* base = (const float4*)emb + (c4 >> 2);

    float4 acc = make_float4(0.f, 0.f, 0.f, 0.f);
#pragma unroll 4
    for (int t = s + r; t < e; t += 8) {
        float4 v = __ldcs(base + (size_t)t * 64);
        acc.x += v.x; acc.y += v.y; acc.z += v.z; acc.w += v.w;
    }
    *(float4*)&red[r][c4] = acc;
    __syncthreads();

    if (tid < 256) {
        float sum = 0.f;
#pragma unroll
        for (int j = 0; j < 8; ++j) sum += red[j][tid];
        g_mean[(size_t)n * D_DIM + tid] = sum / fmaxf((float)(e - s), 1.f);
    }
}

// ---------------------------------------------------------------------------
// Pass 2: g_tg = tanh(g_mean @ W). BM=128, BN=64, BK=16, 256 threads.
// Accumulators are 4 row-pairs x 4 cols of packed f32x2 (FFMA2): A row-pairs
// read directly as ulonglong2 from As; B scalar duplicated into b64.
// ---------------------------------------------------------------------------
__global__ void k_gemm_tanh(const float* __restrict__ W) {
    __shared__ __align__(16) float As[16][128];
    __shared__ __align__(16) float Bs[16][64];
    int tid = threadIdx.x;
    int tx = tid & 15, ty = tid >> 4;
    int bm = blockIdx.x * 128, bn = blockIdx.y * 64;

    int br  = tid >> 4;
    int bc4 = (tid & 15) * 4;

    unsigned long long acc2[4][4] = {};   // [row-pair][col], packed (even,odd)
    for (int k0 = 0; k0 < 256; k0 += 16) {
#pragma unroll
        for (int q = 0; q < 2; ++q) {
            int slot = tid * 2 + q;
            int row = slot >> 2;
            int kq  = (slot & 3) * 4;
            float4 av = *(const float4*)(g_mean + (size_t)(bm + row) * 256 + k0 + kq);
            As[kq + 0][row] = av.x;
            As[kq + 1][row] = av.y;
            As[kq + 2][row] = av.z;
            As[kq + 3][row] = av.w;
        }
        float4 bv = *(const float4*)(W + (size_t)(k0 + br) * 256 + bn + bc4);
        *(float4*)&Bs[br][bc4] = bv;
        __syncthreads();
#pragma unroll
        for (int k = 0; k < 16; ++k) {
            ulonglong2 apA = *(const ulonglong2*)&As[k][ty * 8];
            ulonglong2 apB = *(const ulonglong2*)&As[k][ty * 8 + 4];
            float4 b = *(const float4*)&Bs[k][tx * 4];
            unsigned long long bd[4];
            unsigned int b0 = __float_as_uint(b.x), b1 = __float_as_uint(b.y);
            unsigned int b2 = __float_as_uint(b.z), b3 = __float_as_uint(b.w);
            asm("mov.b64 %0, {%1, %1};" : "=l"(bd[0]) : "r"(b0));
            asm("mov.b64 %0, {%1, %1};" : "=l"(bd[1]) : "r"(b1));
            asm("mov.b64 %0, {%1, %1};" : "=l"(bd[2]) : "r"(b2));
            asm("mov.b64 %0, {%1, %1};" : "=l"(bd[3]) : "r"(b3));
#pragma unroll
            for (int j = 0; j < 4; ++j) {
                FFMA2(acc2[0][j], apA.x, bd[j]);
                FFMA2(acc2[1][j], apA.y, bd[j]);
                FFMA2(acc2[2][j], apB.x, bd[j]);
                FFMA2(acc2[3][j], apB.y, bd[j]);
            }
        }
        __syncthreads();
    }
#pragma unroll
    for (int i2 = 0; i2 < 4; ++i2) {
        float lo[4], hi[4];
#pragma unroll
        for (int j = 0; j < 4; ++j)
            asm("mov.b64 {%0, %1}, %2;" : "=f"(lo[j]), "=f"(hi[j]) : "l"(acc2[i2][j]));
        float4 o0, o1;
        o0.x = tanhf(lo[0]); o0.y = tanhf(lo[1]); o0.z = tanhf(lo[2]); o0.w = tanhf(lo[3]);
        o1.x = tanhf(hi[0]); o1.y = tanhf(hi[1]); o1.z = tanhf(hi[2]); o1.w = tanhf(hi[3]);
        int row = bm + ty * 8 + i2 * 2;
        *(float4*)(g_tg + (size_t)row * 256 + bn + tx * 4)       = o0;
        *(float4*)(g_tg + (size_t)(row + 1) * 256 + bn + tx * 4) = o1;
    }
}

// ---------------------------------------------------------------------------
// Pass 3 (fused): scores + weighted segment sum + broadcast. One block per
// segment; warp processes two tokens per iteration; per-warp smem rows +
// tree combine (no shared atomics).
// ---------------------------------------------------------------------------
__global__ void __launch_bounds__(256, 6)
k_score_rep_bcast(const float* __restrict__ emb, float* __restrict__ out) {
    int n = blockIdx.x, tid = threadIdx.x;
    __shared__ __align__(16) float stg[256];
    __shared__ __align__(16) float redw[8][256];
    __shared__ __align__(16) float srep[256];
    int s = g_segstart[n], e = g_segstart[n + 1];
    stg[tid] = g_tg[(size_t)n * 256 + tid];
    __syncthreads();
    int lane = tid & 31, w = tid >> 5;

    float4 tga = *(const float4*)&stg[lane * 8];
    float4 tgb = *(const float4*)&stg[lane * 8 + 4];
    float4 accA = make_float4(0.f, 0.f, 0.f, 0.f);
    float4 accB = make_float4(0.f, 0.f, 0.f, 0.f);

    const float4* base = (const float4*)emb + lane * 2;

    int t = s + 2 * w;
    for (; t + 1 < e; t += 16) {
        float4 a0 = __ldcs(base + (size_t)(t + 0) * 64);
        float4 b0 = __ldcs(base + (size_t)(t + 0) * 64 + 1);
        float4 a1 = __ldcs(base + (size_t)(t + 1) * 64);
        float4 b1 = __ldcs(base + (size_t)(t + 1) * 64 + 1);
        float d0 = a0.x*tga.x + a0.y*tga.y + a0.z*tga.z + a0.w*tga.w
                 + b0.x*tgb.x + b0.y*tgb.y + b0.z*tgb.z + b0.w*tgb.w;
        float d1 = a1.x*tga.x + a1.y*tga.y + a1.z*tga.z + a1.w*tga.w
                 + b1.x*tgb.x + b1.y*tgb.y + b1.z*tgb.z + b1.w*tgb.w;
#pragma unroll
        for (int off = 16; off; off >>= 1) {
            d0 += __shfl_xor_sync(0xffffffffu, d0, off);
            d1 += __shfl_xor_sync(0xffffffffu, d1, off);
        }
        float s0 = 1.f / (1.f + __expf(-d0));
        float s1 = 1.f / (1.f + __expf(-d1));
        accA.x += a0.x*s0 + a1.x*s1;
        accA.y += a0.y*s0 + a1.y*s1;
        accA.z += a0.z*s0 + a1.z*s1;
        accA.w += a0.w*s0 + a1.w*s1;
        accB.x += b0.x*s0 + b1.x*s1;
        accB.y += b0.y*s0 + b1.y*s1;
        accB.z += b0.z*s0 + b1.z*s1;
        accB.w += b0.w*s0 + b1.w*s1;
    }
    if (t < e) {
        float4 a0 = __ldcs(base + (size_t)t * 64);
        float4 b0 = __ldcs(base + (size_t)t * 64 + 1);
        float d0 = a0.x*tga.x + a0.y*tga.y + a0.z*tga.z + a0.w*tga.w
                 + b0.x*tgb.x + b0.y*tgb.y + b0.z*tgb.z + b0.w*tgb.w;
#pragma unroll
        for (int off = 16; off; off >>= 1)
            d0 += __shfl_xor_sync(0xffffffffu, d0, off);
        float s0 = 1.f / (1.f + __expf(-d0));
        accA.x += a0.x*s0; accA.y += a0.y*s0;
        accA.z += a0.z*s0; accA.w += a0.w*s0;
        accB.x += b0.x*s0; accB.y += b0.y*s0;
        accB.z += b0.z*s0; accB.w += b0.w*s0;
    }
    *(float4*)&redw[w][lane * 8]     = accA;
    *(float4*)&redw[w][lane * 8 + 4] = accB;
    __syncthreads();
    float sum = 0.f;
#pragma unroll
    for (int j = 0; j < 8; ++j) sum += redw[j][tid];
    srep[tid] = sum;
    __syncthreads();

    int c = tid & 63;
    int r = tid >> 6;
    float4 rv = *(const float4*)&srep[c * 4];
    float4* ob = (float4*)out + c;
    for (int tt = s + r; tt < e; tt += 4)
        __stcs(ob + (size_t)tt * 64, rv);
}

extern "C" void kernel_launch(void* const* d_in, const int* in_sizes, int n_in,
                              void* d_out, int out_size) {
    const float* emb = (const float*)d_in[0];
    const float* W   = (const float*)d_in[1];
    const int*   obj = (const int*)d_in[2];
    float*       out = (float*)d_out;

    k_bounds<<<(T_TOK + 255) / 256, 256>>>(obj);
    k_segmean<<<N_SEG, 512>>>(emb);
    k_gemm_tanh<<<dim3(N_SEG / 128, D_DIM / 64), 256>>>(W);
    k_score_rep_bcast<<<N_SEG, 256>>>(emb, out);
}

// round 10
// speedup vs baseline: 1.1801x; 1.1801x over previous
#include <cuda_runtime.h>
#include <math.h>

#define T_TOK 524288
#define D_DIM 256
#define N_SEG 8192

__device__ __align__(16) float g_mean[N_SEG * D_DIM];
__device__ __align__(16) float g_tg[N_SEG * D_DIM];
__device__ int g_segstart[N_SEG + 1];

// ---------------------------------------------------------------------------
// Pass 0: segment boundaries from sorted obj.
// ---------------------------------------------------------------------------
__global__ void k_bounds(const int* __restrict__ obj) {
    int t = blockIdx.x * blockDim.x + threadIdx.x;
    if (t >= T_TOK) return;
    if (t == 0) {
        int v0 = obj[0];
        for (int j = 0; j <= v0; ++j) g_segstart[j] = 0;
        int vl = obj[T_TOK - 1];
        for (int j = vl + 1; j <= N_SEG; ++j) g_segstart[j] = T_TOK;
    } else {
        int p = obj[t - 1], c = obj[t];
        for (int j = p + 1; j <= c; ++j) g_segstart[j] = t;
    }
}

// ---------------------------------------------------------------------------
// Pass 1: per-segment mean. One 512-thread block per segment; thread owns
// float4 column (tid&63)*4 of row-group tid>>6 (8 groups, stride 8).
// ---------------------------------------------------------------------------
__global__ void __launch_bounds__(512)
k_segmean(const float* __restrict__ emb) {
    int n = blockIdx.x, tid = threadIdx.x;
    __shared__ __align__(16) float red[8][256];
    int s = g_segstart[n], e = g_segstart[n + 1];

    int r = tid >> 6;
    int c4 = (tid & 63) * 4;
    const float4* base = (const float4*)emb + (c4 >> 2);

    float4 acc = make_float4(0.f, 0.f, 0.f, 0.f);
#pragma unroll 4
    for (int t = s + r; t < e; t += 8) {
        float4 v = __ldcs(base + (size_t)t * 64);
        acc.x += v.x; acc.y += v.y; acc.z += v.z; acc.w += v.w;
    }
    *(float4*)&red[r][c4] = acc;
    __syncthreads();

    if (tid < 256) {
        float sum = 0.f;
#pragma unroll
        for (int j = 0; j < 8; ++j) sum += red[j][tid];
        g_mean[(size_t)n * D_DIM + tid] = sum / fmaxf((float)(e - s), 1.f);
    }
}

// ---------------------------------------------------------------------------
// Pass 2: g_tg = tanh(g_mean @ W). BM=128, BN=64, BK=16, 256 threads, 8x4
// scalar register tile, DOUBLE-BUFFERED smem (1 sync per K-slab).
// ---------------------------------------------------------------------------
__global__ void k_gemm_tanh(const float* __restrict__ W) {
    __shared__ __align__(16) float As[2][16][128];
    __shared__ __align__(16) float Bs[2][16][64];
    int tid = threadIdx.x;
    int tx = tid & 15, ty = tid >> 4;
    int bm = blockIdx.x * 128, bn = blockIdx.y * 64;

    int br  = tid >> 4;
    int bc4 = (tid & 15) * 4;
    int slot0 = tid * 2, slot1 = tid * 2 + 1;
    int arow0 = slot0 >> 2, akq0 = (slot0 & 3) * 4;
    int arow1 = slot1 >> 2, akq1 = (slot1 & 3) * 4;

    // preload slab 0
    float4 av0 = *(const float4*)(g_mean + (size_t)(bm + arow0) * 256 + akq0);
    float4 av1 = *(const float4*)(g_mean + (size_t)(bm + arow1) * 256 + akq1);
    float4 bv  = *(const float4*)(W + (size_t)br * 256 + bn + bc4);
    As[0][akq0 + 0][arow0] = av0.x; As[0][akq0 + 1][arow0] = av0.y;
    As[0][akq0 + 2][arow0] = av0.z; As[0][akq0 + 3][arow0] = av0.w;
    As[0][akq1 + 0][arow1] = av1.x; As[0][akq1 + 1][arow1] = av1.y;
    As[0][akq1 + 2][arow1] = av1.z; As[0][akq1 + 3][arow1] = av1.w;
    *(float4*)&Bs[0][br][bc4] = bv;
    __syncthreads();

    float acc[8][4] = {};
#pragma unroll
    for (int it = 0; it < 16; ++it) {
        int buf = it & 1;
        if (it < 15) {
            int k0 = (it + 1) * 16;
            av0 = *(const float4*)(g_mean + (size_t)(bm + arow0) * 256 + k0 + akq0);
            av1 = *(const float4*)(g_mean + (size_t)(bm + arow1) * 256 + k0 + akq1);
            bv  = *(const float4*)(W + (size_t)(k0 + br) * 256 + bn + bc4);
        }
#pragma unroll
        for (int k = 0; k < 16; ++k) {
            float a[8], b[4];
            *(float4*)&a[0] = *(const float4*)&As[buf][k][ty * 8];
            *(float4*)&a[4] = *(const float4*)&As[buf][k][ty * 8 + 4];
            *(float4*)b = *(const float4*)&Bs[buf][k][tx * 4];
#pragma unroll
            for (int i = 0; i < 8; ++i)
#pragma unroll
                for (int j = 0; j < 4; ++j)
                    acc[i][j] += a[i] * b[j];
        }
        if (it < 15) {
            int nb = buf ^ 1;
            As[nb][akq0 + 0][arow0] = av0.x; As[nb][akq0 + 1][arow0] = av0.y;
            As[nb][akq0 + 2][arow0] = av0.z; As[nb][akq0 + 3][arow0] = av0.w;
            As[nb][akq1 + 0][arow1] = av1.x; As[nb][akq1 + 1][arow1] = av1.y;
            As[nb][akq1 + 2][arow1] = av1.z; As[nb][akq1 + 3][arow1] = av1.w;
            *(float4*)&Bs[nb][br][bc4] = bv;
            __syncthreads();
        }
    }
#pragma unroll
    for (int i = 0; i < 8; ++i) {
        float4 o;
        o.x = tanhf(acc[i][0]);
        o.y = tanhf(acc[i][1]);
        o.z = tanhf(acc[i][2]);
        o.w = tanhf(acc[i][3]);
        *(float4*)(g_tg + (size_t)(bm + ty * 8 + i) * 256 + bn + tx * 4) = o;
    }
}

// ---------------------------------------------------------------------------
// Pass 3 (fused): scores + weighted segment sum + broadcast. One block per
// segment; warp processes two tokens per iteration; per-warp smem rows +
// tree combine (no shared atomics).
// ---------------------------------------------------------------------------
__global__ void __launch_bounds__(256, 6)
k_score_rep_bcast(const float* __restrict__ emb, float* __restrict__ out) {
    int n = blockIdx.x, tid = threadIdx.x;
    __shared__ __align__(16) float stg[256];
    __shared__ __align__(16) float redw[8][256];
    __shared__ __align__(16) float srep[256];
    int s = g_segstart[n], e = g_segstart[n + 1];
    stg[tid] = g_tg[(size_t)n * 256 + tid];
    __syncthreads();
    int lane = tid & 31, w = tid >> 5;

    float4 tga = *(const float4*)&stg[lane * 8];
    float4 tgb = *(const float4*)&stg[lane * 8 + 4];
    float4 accA = make_float4(0.f, 0.f, 0.f, 0.f);
    float4 accB = make_float4(0.f, 0.f, 0.f, 0.f);

    const float4* base = (const float4*)emb + lane * 2;

    int t = s + 2 * w;
    for (; t + 1 < e; t += 16) {
        float4 a0 = __ldcs(base + (size_t)(t + 0) * 64);
        float4 b0 = __ldcs(base + (size_t)(t + 0) * 64 + 1);
        float4 a1 = __ldcs(base + (size_t)(t + 1) * 64);
        float4 b1 = __ldcs(base + (size_t)(t + 1) * 64 + 1);
        float d0 = a0.x*tga.x + a0.y*tga.y + a0.z*tga.z + a0.w*tga.w
                 + b0.x*tgb.x + b0.y*tgb.y + b0.z*tgb.z + b0.w*tgb.w;
        float d1 = a1.x*tga.x + a1.y*tga.y + a1.z*tga.z + a1.w*tga.w
                 + b1.x*tgb.x + b1.y*tgb.y + b1.z*tgb.z + b1.w*tgb.w;
#pragma unroll
        for (int off = 16; off; off >>= 1) {
            d0 += __shfl_xor_sync(0xffffffffu, d0, off);
            d1 += __shfl_xor_sync(0xffffffffu, d1, off);
        }
        float s0 = 1.f / (1.f + __expf(-d0));
        float s1 = 1.f / (1.f + __expf(-d1));
        accA.x += a0.x*s0 + a1.x*s1;
        accA.y += a0.y*s0 + a1.y*s1;
        accA.z += a0.z*s0 + a1.z*s1;
        accA.w += a0.w*s0 + a1.w*s1;
        accB.x += b0.x*s0 + b1.x*s1;
        accB.y += b0.y*s0 + b1.y*s1;
        accB.z += b0.z*s0 + b1.z*s1;
        accB.w += b0.w*s0 + b1.w*s1;
    }
    if (t < e) {
        float4 a0 = __ldcs(base + (size_t)t * 64);
        float4 b0 = __ldcs(base + (size_t)t * 64 + 1);
        float d0 = a0.x*tga.x + a0.y*tga.y + a0.z*tga.z + a0.w*tga.w
                 + b0.x*tgb.x + b0.y*tgb.y + b0.z*tgb.z + b0.w*tgb.w;
#pragma unroll
        for (int off = 16; off; off >>= 1)
            d0 += __shfl_xor_sync(0xffffffffu, d0, off);
        float s0 = 1.f / (1.f + __expf(-d0));
        accA.x += a0.x*s0; accA.y += a0.y*s0;
        accA.z += a0.z*s0; accA.w += a0.w*s0;
        accB.x += b0.x*s0; accB.y += b0.y*s0;
        accB.z += b0.z*s0; accB.w += b0.w*s0;
    }
    *(float4*)&redw[w][lane * 8]     = accA;
    *(float4*)&redw[w][lane * 8 + 4] = accB;
    __syncthreads();
    float sum = 0.f;
#pragma unroll
    for (int j = 0; j < 8; ++j) sum += redw[j][tid];
    srep[tid] = sum;
    __syncthreads();

    int c = tid & 63;
    int r = tid >> 6;
    float4 rv = *(const float4*)&srep[c * 4];
    float4* ob = (float4*)out + c;
    for (int tt = s + r; tt < e; tt += 4)
        __stcs(ob + (size_t)tt * 64, rv);
}

extern "C" void kernel_launch(void* const* d_in, const int* in_sizes, int n_in,
                              void* d_out, int out_size) {
    const float* emb = (const float*)d_in[0];
    const float* W   = (const float*)d_in[1];
    const int*   obj = (const int*)d_in[2];
    float*       out = (float*)d_out;

    k_bounds<<<(T_TOK + 255) / 256, 256>>>(obj);
    k_segmean<<<N_SEG, 512>>>(emb);
    k_gemm_tanh<<<dim3(N_SEG / 128, D_DIM / 64), 256>>>(W);
    k_score_rep_bcast<<<N_SEG, 256>>>(emb, out);
}